// round 7
// baseline (speedup 1.0000x reference)
#include <cuda_runtime.h>

// SSIM over (64,1,512,512) f32, 11x11 zero-padded box filters.
// Separable box filter, R5 revision:
//   - __launch_bounds__(128,8): target <=64 regs -> 8 CTAs/SM (32 warps).
//   - Direct STG.64 epilogue from the horizontal stage (pairs of outputs in
//     registers): removes the `so` staging tile, the store pass, and one
//     __syncthreads per chunk. smem 20.4KB -> 16.5KB.
//   - Staged quantities stay packed float4 (sx, sy, s(x^2+y^2), s(x*y)).

namespace {
constexpr int W = 512, H = 512;
constexpr int PAD = 5;                 // win=11 -> halo 5
constexpr int TX = 118;                // output cols per strip
constexpr int NSTRIP = 5;              // ceil(512/118)
constexpr int THREADS = 128;           // TX + 2*PAD
constexpr int RCHUNK = 8;              // rows staged in smem per iteration
constexpr int RBLOCK = 64;             // output rows per CTA
constexpr int PITCH = 129;             // vs pitch (float4s per row), conflict-free
constexpr float INV_N = 1.0f / 121.0f;
constexpr float COV = 121.0f / 120.0f;
}

__device__ __forceinline__ float ld0(const float* __restrict__ p, int r, int gcol, bool cv) {
    if (cv && r >= 0 && r < H) return __ldg(p + r * W + gcol);
    return 0.0f;
}

__global__ __launch_bounds__(THREADS, 8) void ssim_kernel(
    const float* __restrict__ img, const float* __restrict__ ref,
    const float* __restrict__ drange, float* __restrict__ out)
{
    __shared__ float4 vs4[RCHUNK][PITCH];    // (sx, sy, s(xx+yy), sxy)

    const int tid   = threadIdx.x;
    const int strip = blockIdx.x;
    const int rb    = blockIdx.y;
    const int b     = blockIdx.z;

    const float* ip = img + (size_t)b * H * W;
    const float* rp = ref + (size_t)b * H * W;
    float*       op = out + (size_t)b * H * W;

    const float dr = __ldg(drange + b);
    const float C1 = (0.01f * dr) * (0.01f * dr);
    const float C2 = (0.03f * dr) * (0.03f * dr);

    const int  gcol = strip * TX + tid - PAD;       // column this thread streams
    const bool cv   = (gcol >= 0) && (gcol < W);

    const int r_start = rb * RBLOCK;

    // --- init vertical running sums: rows [r_start-5, r_start+5] ---
    float sx = 0.f, sy = 0.f, sq = 0.f, sxy = 0.f;
    #pragma unroll
    for (int d = -PAD; d <= PAD; ++d) {
        float x = ld0(ip, r_start + d, gcol, cv);
        float y = ld0(rp, r_start + d, gcol, cv);
        sx += x; sy += y;
        sq  = fmaf(x, x, sq);
        sq  = fmaf(y, y, sq);
        sxy = fmaf(x, y, sxy);
    }

    const int hrow = tid & (RCHUNK - 1);   // 0..7
    const int hch  = tid >> 3;             // 0..15
    const int c0   = hch * 8;              // 15 chunks of 8 cover 118 (hch=15 idle)
    const bool hact = (c0 < TX);
    const int gcb  = strip * TX + c0;      // global col base for this lane's chunk

    for (int ck = 0; ck < RBLOCK / RCHUNK; ++ck) {
        const int r0 = r_start + ck * RCHUNK;

        // --- vertical stage: stage 8 rows of packed vertical sums ---
        #pragma unroll
        for (int i = 0; i < RCHUNK; ++i) {
            vs4[i][tid] = make_float4(sx, sy, sq, sxy);
            const int r = r0 + i;
            float xn = ld0(ip, r + PAD + 1, gcol, cv);
            float yn = ld0(rp, r + PAD + 1, gcol, cv);
            float xo = ld0(ip, r - PAD, gcol, cv);        // L1/L2 hit (loaded 11 rows ago)
            float yo = ld0(rp, r - PAD, gcol, cv);
            sx += xn - xo;
            sy += yn - yo;
            sq  += (xn * xn + yn * yn) - (xo * xo + yo * yo);
            sxy += xn * yn - xo * yo;
        }
        __syncthreads();

        // --- horizontal sliding sums + SSIM + direct paired stores ---
        if (hact) {
            float hx = 0.f, hy = 0.f, hq = 0.f, hxy = 0.f;
            #pragma unroll
            for (int j = 0; j < 11; ++j) {
                float4 v = vs4[hrow][c0 + j];
                hx += v.x; hy += v.y; hq += v.z; hxy += v.w;
            }
            float* orow = op + (r0 + hrow) * W;
            float pv = 0.f;
            #pragma unroll
            for (int k = 0; k < 8; ++k) {
                const int c = c0 + k;
                if (c < TX) {
                    float ux  = hx  * INV_N;
                    float uy  = hy  * INV_N;
                    float uq  = hq  * INV_N;
                    float uxy = hxy * INV_N;
                    float uxux = ux * ux;
                    float uyuy = uy * uy;
                    float vxy = COV * (uxy - ux * uy);
                    float A1 = 2.f * ux * uy + C1;
                    float A2 = 2.f * vxy + C2;
                    float B1 = uxux + uyuy + C1;
                    float B2 = COV * (uq - uxux - uyuy) + C2;
                    float s  = __fdividef(A1 * A2, B1 * B2);
                    if (k & 1) {
                        // pair (gcb+k-1, gcb+k): start is even -> 8B aligned;
                        // never straddles TX or W (both even).
                        if (gcb + k < W)
                            *reinterpret_cast<float2*>(orow + gcb + k - 1) =
                                make_float2(pv, s);
                    } else {
                        pv = s;
                    }
                    if (k < 7) {    // last slide feeds nothing
                        float4 va = vs4[hrow][c + 11];
                        float4 vb = vs4[hrow][c];
                        hx  += va.x - vb.x;
                        hy  += va.y - vb.y;
                        hq  += va.z - vb.z;
                        hxy += va.w - vb.w;
                    }
                }
            }
        }
        __syncthreads();
    }
}

extern "C" void kernel_launch(void* const* d_in, const int* in_sizes, int n_in,
                              void* d_out, int out_size) {
    const float* img = (const float*)d_in[0];
    const float* ref = (const float*)d_in[1];
    const float* dr  = (const float*)d_in[2];
    float* out = (float*)d_out;
    const int B = in_sizes[2];            // batch = data_range element count (64)
    dim3 grid(NSTRIP, H / RBLOCK, B);
    ssim_kernel<<<grid, THREADS>>>(img, ref, dr, out);
}

// round 8
// speedup vs baseline: 1.2122x; 1.2122x over previous
#include <cuda_runtime.h>

// SSIM over (64,1,512,512) f32, 11x11 zero-padded box filters.
// Separable box filter, R7 revision (revert of R5's scattered-store regression):
//   - R4 structure: float4-packed staging (sx, sy, s(x^2+y^2), s(x*y)),
//     RCHUNK=8, RBLOCK=64, staged coalesced store pass, 7 CTAs/SM.
//   - NEW: `so` is double-buffered (parity by chunk) -> 2 __syncthreads per
//     chunk instead of 3, and the store pass of chunk ck-1 is issued UNDER the
//     vertical-stage LDGs of chunk ck (latency overlap).
//   - smem 24.1KB, regs ~70 -> 7 CTAs/SM unchanged.

namespace {
constexpr int W = 512, H = 512;
constexpr int PAD = 5;                 // win=11 -> halo 5
constexpr int TX = 118;                // output cols per strip
constexpr int NSTRIP = 5;              // ceil(512/118)
constexpr int THREADS = 128;           // TX + 2*PAD
constexpr int RCHUNK = 8;              // rows staged in smem per iteration
constexpr int RBLOCK = 64;             // output rows per CTA
constexpr int NCHUNK = RBLOCK / RCHUNK;
constexpr int PITCH = 129;             // vs pitch (float4s per row), conflict-free
constexpr int SO_PITCH = 119;          // staging pitch (conflict-free vs (hrow,hch))
constexpr float INV_N = 1.0f / 121.0f;
constexpr float COV = 121.0f / 120.0f;
}

__device__ __forceinline__ float ld0(const float* __restrict__ p, int r, int gcol, bool cv) {
    if (cv && r >= 0 && r < H) return __ldg(p + r * W + gcol);
    return 0.0f;
}

__global__ __launch_bounds__(THREADS, 7) void ssim_kernel(
    const float* __restrict__ img, const float* __restrict__ ref,
    const float* __restrict__ drange, float* __restrict__ out)
{
    __shared__ float4 vs4[RCHUNK][PITCH];       // (sx, sy, s(xx+yy), sxy)
    __shared__ float  so[2][RCHUNK][SO_PITCH];  // double-buffered staging tile

    const int tid   = threadIdx.x;
    const int strip = blockIdx.x;
    const int rb    = blockIdx.y;
    const int b     = blockIdx.z;

    const float* ip = img + (size_t)b * H * W;
    const float* rp = ref + (size_t)b * H * W;
    float*       op = out + (size_t)b * H * W;

    const float dr = __ldg(drange + b);
    const float C1 = (0.01f * dr) * (0.01f * dr);
    const float C2 = (0.03f * dr) * (0.03f * dr);

    const int  gcol = strip * TX + tid - PAD;       // column this thread streams
    const bool cv   = (gcol >= 0) && (gcol < W);

    const int r_start = rb * RBLOCK;

    // --- init vertical running sums: rows [r_start-5, r_start+5] ---
    float sx = 0.f, sy = 0.f, sq = 0.f, sxy = 0.f;
    #pragma unroll
    for (int d = -PAD; d <= PAD; ++d) {
        float x = ld0(ip, r_start + d, gcol, cv);
        float y = ld0(rp, r_start + d, gcol, cv);
        sx += x; sy += y;
        sq  = fmaf(x, x, sq);
        sq  = fmaf(y, y, sq);
        sxy = fmaf(x, y, sxy);
    }

    const int hrow = tid & (RCHUNK - 1);   // 0..7
    const int hch  = tid >> 3;             // 0..15
    const int c0   = hch * 8;              // 15 chunks of 8 cover 118 (hch=15 idle)
    const bool hact = (c0 < TX);

    const int  ocol   = strip * TX + tid;  // store-pass column for this thread
    const bool st_act = (tid < TX) && (ocol < W);

    for (int ck = 0; ck < NCHUNK; ++ck) {
        const int r0 = r_start + ck * RCHUNK;

        // --- V(ck): stage 8 rows of packed vertical sums (LDGs issue first) ---
        #pragma unroll
        for (int i = 0; i < RCHUNK; ++i) {
            vs4[i][tid] = make_float4(sx, sy, sq, sxy);
            const int r = r0 + i;
            float xn = ld0(ip, r + PAD + 1, gcol, cv);
            float yn = ld0(rp, r + PAD + 1, gcol, cv);
            float xo = ld0(ip, r - PAD, gcol, cv);        // L1/L2 hit (loaded 11 rows ago)
            float yo = ld0(rp, r - PAD, gcol, cv);
            sx += xn - xo;
            sy += yn - yo;
            sq  += (xn * xn + yn * yn) - (xo * xo + yo * yo);
            sxy += xn * yn - xo * yo;
        }

        // --- S(ck-1): coalesced store pass, overlapped under V's LDG latency ---
        if (ck > 0 && st_act) {
            const int rp0 = r_start + (ck - 1) * RCHUNK;
            const float (* __restrict__ sp)[SO_PITCH] = so[(ck - 1) & 1];
            #pragma unroll
            for (int rr = 0; rr < RCHUNK; ++rr)
                op[(rp0 + rr) * W + ocol] = sp[rr][tid];
        }
        __syncthreads();   // vs4 RAW (V->H); also orders S(ck-1) before H(ck)

        // --- H(ck): horizontal sliding sums + SSIM -> so[ck&1] ---
        if (hact) {
            float (* __restrict__ sw)[SO_PITCH] = so[ck & 1];
            float hx = 0.f, hy = 0.f, hq = 0.f, hxy = 0.f;
            #pragma unroll
            for (int j = 0; j < 11; ++j) {
                float4 v = vs4[hrow][c0 + j];
                hx += v.x; hy += v.y; hq += v.z; hxy += v.w;
            }
            #pragma unroll
            for (int k = 0; k < 8; ++k) {
                const int c = c0 + k;
                if (c < TX) {
                    float ux  = hx  * INV_N;
                    float uy  = hy  * INV_N;
                    float uq  = hq  * INV_N;
                    float uxy = hxy * INV_N;
                    float uxux = ux * ux;
                    float uyuy = uy * uy;
                    float vxy = COV * (uxy - ux * uy);
                    float A1 = 2.f * ux * uy + C1;
                    float A2 = 2.f * vxy + C2;
                    float B1 = uxux + uyuy + C1;
                    float B2 = COV * (uq - uxux - uyuy) + C2;
                    sw[hrow][c] = __fdividef(A1 * A2, B1 * B2);
                    if (k < 7) {    // last slide feeds nothing
                        float4 va = vs4[hrow][c + 11];
                        float4 vb = vs4[hrow][c];
                        hx  += va.x - vb.x;
                        hy  += va.y - vb.y;
                        hq  += va.z - vb.z;
                        hxy += va.w - vb.w;
                    }
                }
            }
        }
        __syncthreads();   // so RAW (H->S next iter); vs4 WAR (H before next V)
    }

    // --- epilogue: store pass for the final chunk ---
    if (st_act) {
        const int rp0 = r_start + (NCHUNK - 1) * RCHUNK;
        const float (* __restrict__ sp)[SO_PITCH] = so[(NCHUNK - 1) & 1];
        #pragma unroll
        for (int rr = 0; rr < RCHUNK; ++rr)
            op[(rp0 + rr) * W + ocol] = sp[rr][tid];
    }
}

extern "C" void kernel_launch(void* const* d_in, const int* in_sizes, int n_in,
                              void* d_out, int out_size) {
    const float* img = (const float*)d_in[0];
    const float* ref = (const float*)d_in[1];
    const float* dr  = (const float*)d_in[2];
    float* out = (float*)d_out;
    const int B = in_sizes[2];            // batch = data_range element count (64)
    dim3 grid(NSTRIP, H / RBLOCK, B);
    ssim_kernel<<<grid, THREADS>>>(img, ref, dr, out);
}